// round 6
// baseline (speedup 1.0000x reference)
#include <cuda_runtime.h>
#include <cuda_bf16.h>
#include <mma.h>
#include <math.h>
#include <stdint.h>

using namespace nvcuda;

#define B_ 4
#define C_ 96
#define H_ 256
#define W_ 256
#define HW (H_*W_)
#define LDA 104
#define LDB 136

// Scratch (allocation-free rule: __device__ globals)
__device__ float g_xn[B_*C_*HW];   // layernorm output
__device__ float g_e0[B_*C_*HW];   // e0 pointwise pre-activation
__device__ float g_xa[B_*C_*HW];   // x_adaptive

using FragA = wmma::fragment<wmma::matrix_a, 16, 16, 8, wmma::precision::tf32, wmma::row_major>;
using FragB = wmma::fragment<wmma::matrix_b, 16, 16, 8, wmma::precision::tf32, wmma::row_major>;
using FragC = wmma::fragment<wmma::accumulator, 16, 16, 8, float>;

__device__ __forceinline__ float to_tf32(float v) { return wmma::__float_to_tf32(v); }

// C[96 x 128] += A[96 x 96] (smem [96][LDA]) * B[96 x 128] (smem [96][LDB])
// Warp (wm 0..1, wn 0..3): rows wm*48..+48, cols wn*32..+32.
__device__ __forceinline__ void gemm_t(const float* a, const float* b,
                                       FragC (&acc)[3][2], int wm, int wn)
{
    #pragma unroll 1
    for (int k = 0; k < 12; k++) {
        FragB bf[2];
        #pragma unroll
        for (int nf = 0; nf < 2; nf++)
            wmma::load_matrix_sync(bf[nf], b + (k * 8) * LDB + wn * 32 + nf * 16, LDB);
        #pragma unroll
        for (int mf = 0; mf < 3; mf++) {
            FragA af;
            wmma::load_matrix_sync(af, a + (wm * 48 + mf * 16) * LDA + k * 8, LDA);
            #pragma unroll
            for (int nf = 0; nf < 2; nf++)
                wmma::mma_sync(acc[mf][nf], af, bf[nf], acc[mf][nf]);
        }
    }
}

__device__ __forceinline__ void zero_acc(FragC (&acc)[3][2]) {
    #pragma unroll
    for (int mf = 0; mf < 3; mf++)
        #pragma unroll
        for (int nf = 0; nf < 2; nf++) wmma::fill_fragment(acc[mf][nf], 0.f);
}

// ---------------------------------------------------------------------------
// Kernel 1: LayerNorm (writes g_xn) + e0 pointwise (TF32 WMMA) -> g_e0
// smem ~102.5KB -> 2 CTAs/SM
// ---------------------------------------------------------------------------
#define LN_XS   0
#define LN_WS   13056
#define LN_STG  23040
#define LN_MU   25088
#define LN_INV  25216
#define LN_LNW  25344
#define LN_LNB  25440
#define LN_BS   25536
#define LN_FLTS 25632

__global__ __launch_bounds__(256) void k_ln_e0pw(
    const float* __restrict__ x,
    const float* __restrict__ lnw, const float* __restrict__ lnb,
    const float* __restrict__ w, const float* __restrict__ bias)
{
    extern __shared__ float sm[];
    float* xs   = sm + LN_XS;     // [96][136]
    float* ws   = sm + LN_WS;     // [96][104]
    float* stage= sm + LN_STG;    // 8 x 256
    float* mu   = sm + LN_MU;
    float* inv  = sm + LN_INV;
    float* lnws = sm + LN_LNW;
    float* lnbs = sm + LN_LNB;
    float* bs   = sm + LN_BS;

    const int t = threadIdx.x, wid = t >> 5, lane = t & 31;
    const int b = blockIdx.y;
    const int p0 = blockIdx.x * 128;
    const float* xb = x + (size_t)b * C_ * HW + p0;

    for (int i = t; i < 96 * 32; i += 256) {
        int k = i >> 5, c4 = (i & 31) * 4;
        *(float4*)(xs + k * LDB + c4) = *(const float4*)(xb + (size_t)k * HW + c4);
    }
    for (int i = t; i < 2304; i += 256) {
        int idx = i * 4, m = idx / 96, kk = idx % 96;
        float4 v = *(const float4*)(w + idx);
        float* d = ws + m * LDA + kk;
        d[0] = to_tf32(v.x); d[1] = to_tf32(v.y);
        d[2] = to_tf32(v.z); d[3] = to_tf32(v.w);
    }
    if (t < 96) { lnws[t] = lnw[t]; lnbs[t] = lnb[t]; bs[t] = bias[t]; }
    __syncthreads();

    if (t < 128) {
        float s = 0.f, s2 = 0.f;
        #pragma unroll 8
        for (int k = 0; k < 96; k++) {
            float v = xs[k * LDB + t];
            s += v; s2 += v * v;
        }
        float m = s * (1.f / 96.f);
        float var = s2 * (1.f / 96.f) - m * m;
        mu[t] = m;
        inv[t] = rsqrtf(var + 1e-6f);
    }
    __syncthreads();

    float* xnb = g_xn + (size_t)b * C_ * HW + p0;
    for (int i = t; i < 12288; i += 256) {
        int k = i >> 7, p = i & 127;
        float v = (xs[k * LDB + p] - mu[p]) * inv[p] * lnws[k] + lnbs[k];
        xnb[(size_t)k * HW + p] = v;            // full precision for dw convs
        xs[k * LDB + p] = to_tf32(v);           // tf32 for GEMM
    }
    __syncthreads();

    const int wm = wid >> 2, wn = wid & 3;
    FragC acc[3][2];
    zero_acc(acc);
    gemm_t(ws, xs, acc, wm, wn);

    float* st = stage + wid * 256;
    float* gb = g_e0 + (size_t)b * C_ * HW + p0;
    const int r = lane >> 1, cc = (lane & 1) * 8;
    #pragma unroll
    for (int mf = 0; mf < 3; mf++)
        #pragma unroll
        for (int nf = 0; nf < 2; nf++) {
            wmma::store_matrix_sync(st, acc[mf][nf], 16, wmma::mem_row_major);
            __syncwarp();
            int mm = wm * 48 + mf * 16 + r;
            int pp = wn * 32 + nf * 16 + cc;
            float bb = bs[mm];
            float* gp = gb + (size_t)mm * HW + pp;
            const float* sp = st + r * 16 + cc;
            #pragma unroll
            for (int q = 0; q < 8; q++) gp[q] = sp[q] + bb;
            __syncwarp();
        }
}

// ---------------------------------------------------------------------------
// Kernel 2: depthwise experts + mixing + prompt (scalar, unchanged)
// ---------------------------------------------------------------------------
#define TS 32
__global__ __launch_bounds__(256) void k_dw(
    const float* __restrict__ sw,
    const float* __restrict__ prompt,
    const float* __restrict__ w0, const float* __restrict__ b0,
    const float* __restrict__ w1, const float* __restrict__ b1,
    const float* __restrict__ w2, const float* __restrict__ b2)
{
    __shared__ float xs[44 * 44];
    __shared__ float es[34 * 34];

    int c = blockIdx.y, b = blockIdx.z;
    int ty0 = (blockIdx.x / (W_/TS)) * TS;
    int tx0 = (blockIdx.x % (W_/TS)) * TS;
    const float* xn = g_xn + ((size_t)(b * C_ + c)) * HW;
    const float* ep = g_e0 + ((size_t)(b * C_ + c)) * HW;

    for (int i = threadIdx.x; i < 44*44; i += 256) {
        int yy = ty0 - 6 + i / 44, xx = tx0 - 6 + i % 44;
        xs[i] = (yy >= 0 && yy < H_ && xx >= 0 && xx < W_) ? xn[yy * W_ + xx] : 0.f;
    }
    for (int i = threadIdx.x; i < 34*34; i += 256) {
        int yy = ty0 - 1 + i / 34, xx = tx0 - 1 + i % 34;
        es[i] = (yy >= 0 && yy < H_ && xx >= 0 && xx < W_) ? ep[yy * W_ + xx] : 0.f;
    }

    float k0[9], k1[9], k2[25];
    #pragma unroll
    for (int i = 0; i < 9; i++)  { k0[i] = __ldg(&w0[c*9 + i]);  k1[i] = __ldg(&w1[c*9 + i]); }
    #pragma unroll
    for (int i = 0; i < 25; i++) k2[i] = __ldg(&w2[c*25 + i]);
    float bb0 = __ldg(&b0[c]), bb1 = __ldg(&b1[c]), bb2 = __ldg(&b2[c]);
    float s0 = __ldg(&sw[b*3 + 0]), s1 = __ldg(&sw[b*3 + 1]), s2 = __ldg(&sw[b*3 + 2]);
    float pm = 1.f + __ldg(&prompt[b * C_ + c]);
    __syncthreads();

    float* outp = g_xa + ((size_t)(b * C_ + c)) * HW;
    #pragma unroll
    for (int k = 0; k < 4; k++) {
        int li = threadIdx.x + k * 256;
        int py = li / TS, px = li % TS;
        float e0v = bb0;
        #pragma unroll
        for (int ky = 0; ky < 3; ky++)
            #pragma unroll
            for (int kx = 0; kx < 3; kx++)
                e0v += k0[ky*3 + kx] * es[(py + ky) * 34 + (px + kx)];
        float e1v = bb1;
        #pragma unroll
        for (int ky = 0; ky < 3; ky++)
            #pragma unroll
            for (int kx = 0; kx < 3; kx++)
                e1v += k1[ky*3 + kx] * xs[(py + 4 + 2*ky) * 44 + (px + 4 + 2*kx)];
        float e2v = bb2;
        #pragma unroll
        for (int ky = 0; ky < 5; ky++)
            #pragma unroll
            for (int kx = 0; kx < 5; kx++)
                e2v += k2[ky*5 + kx] * xs[(py + 3*ky) * 44 + (px + 3*kx)];
        outp[(ty0 + py) * W_ + (tx0 + px)] = (s0*e0v + s1*e1v + s2*e2v) * pm;
    }
}

// ---------------------------------------------------------------------------
// Kernel 3: fused proj + FFN:
//   x1 = x + proj(xa) + pb  (kept in SMEM, never hits DRAM)
//   out = x1 + ffn2(gelu(ffn1(x1) + b1)) + b2
// smem ~206KB -> 1 CTA/SM
// ---------------------------------------------------------------------------
#define PF_A    0          /* [96][136]  xa then x1   */
#define PF_W    13056      /* [96][104]  weight chunk */
#define PF_H    23040      /* [192][136] gelu(h)      */
#define PF_STG  49152      /* 8 x 256                 */
#define PF_B1   51200
#define PF_B2   51392
#define PF_PB   51488
#define PF_FLTS 51584

__global__ __launch_bounds__(256, 1) void k_projffn(
    const float* __restrict__ x,
    const float* __restrict__ pw, const float* __restrict__ pb,
    const float* __restrict__ w1, const float* __restrict__ b1v,
    const float* __restrict__ w2, const float* __restrict__ b2v,
    float* __restrict__ out)
{
    extern __shared__ float sm[];
    float* as   = sm + PF_A;
    float* ws   = sm + PF_W;
    float* hs   = sm + PF_H;
    float* stage= sm + PF_STG;
    float* b1s  = sm + PF_B1;
    float* b2s  = sm + PF_B2;
    float* pbs  = sm + PF_PB;

    const int t = threadIdx.x, wid = t >> 5, lane = t & 31;
    const int b = blockIdx.y;
    const int p0 = blockIdx.x * 128;
    const float* ab = g_xa + (size_t)b * C_ * HW + p0;
    const float* xb = x    + (size_t)b * C_ * HW + p0;

    for (int i = t; i < 96 * 32; i += 256) {
        int k = i >> 5, c4 = (i & 31) * 4;
        float4 v = *(const float4*)(ab + (size_t)k * HW + c4);
        float* d = as + k * LDB + c4;
        d[0] = to_tf32(v.x); d[1] = to_tf32(v.y);
        d[2] = to_tf32(v.z); d[3] = to_tf32(v.w);
    }
    for (int i = t; i < 2304; i += 256) {
        int idx = i * 4, m = idx / 96, kk = idx % 96;
        float4 v = *(const float4*)(pw + idx);
        float* d = ws + m * LDA + kk;
        d[0] = to_tf32(v.x); d[1] = to_tf32(v.y);
        d[2] = to_tf32(v.z); d[3] = to_tf32(v.w);
    }
    if (t < 192) b1s[t] = b1v[t];
    if (t < 96)  { b2s[t] = b2v[t]; pbs[t] = pb[t]; }
    __syncthreads();

    const int wm = wid >> 2, wn = wid & 3;
    const int r = lane >> 1, cc = (lane & 1) * 8;
    float* st = stage + wid * 256;

    // ---- proj GEMM ----
    FragC acc[3][2];
    zero_acc(acc);
    gemm_t(ws, as, acc, wm, wn);
    __syncthreads();   // all reads of xa (region A) complete before x1 overwrite

    // epilogue: x1 = acc + pb + x -> region A (full f32; GEMM reads truncate)
    #pragma unroll
    for (int mf = 0; mf < 3; mf++)
        #pragma unroll
        for (int nf = 0; nf < 2; nf++) {
            wmma::store_matrix_sync(st, acc[mf][nf], 16, wmma::mem_row_major);
            __syncwarp();
            int mm = wm * 48 + mf * 16 + r;
            int pp = wn * 32 + nf * 16 + cc;
            float bb = pbs[mm];
            const float* rp = xb + (size_t)mm * HW + pp;
            const float* sp = st + r * 16 + cc;
            float* dp = as + mm * LDB + pp;
            #pragma unroll
            for (int q = 0; q < 8; q++) dp[q] = sp[q] + bb + rp[q];
            __syncwarp();
        }

    // ---- GEMM1: h = gelu(w1 @ x1 + b1), two 96-row chunks ----
    #pragma unroll 1
    for (int oc = 0; oc < 2; oc++) {
        __syncthreads();   // x1 writes done (oc=0) / prior ws readers done (oc=1)
        for (int i = t; i < 2304; i += 256) {
            int idx = i * 4, m = idx / 96, kk = idx % 96;
            float4 v = *(const float4*)(w1 + oc * 9216 + idx);
            float* d = ws + m * LDA + kk;
            d[0] = to_tf32(v.x); d[1] = to_tf32(v.y);
            d[2] = to_tf32(v.z); d[3] = to_tf32(v.w);
        }
        __syncthreads();

        FragC a1[3][2];
        zero_acc(a1);
        gemm_t(ws, as, a1, wm, wn);

        #pragma unroll
        for (int mf = 0; mf < 3; mf++)
            #pragma unroll
            for (int nf = 0; nf < 2; nf++) {
                wmma::store_matrix_sync(st, a1[mf][nf], 16, wmma::mem_row_major);
                __syncwarp();
                int k2 = oc * 96 + wm * 48 + mf * 16 + r;
                int pp = wn * 32 + nf * 16 + cc;
                float bb = b1s[k2];
                const float* sp = st + r * 16 + cc;
                float* dp = hs + k2 * LDB + pp;
                #pragma unroll
                for (int q = 0; q < 8; q++) {
                    float hv = sp[q] + bb;
                    dp[q] = to_tf32(hv * normcdff(hv));
                }
                __syncwarp();
            }
    }

    // ---- GEMM2: out = x1 + w2 @ h + b2, K=192 in two chunks ----
    FragC a2[3][2];
    zero_acc(a2);
    #pragma unroll 1
    for (int kc = 0; kc < 2; kc++) {
        __syncthreads();   // hs complete / prior ws readers done
        for (int i = t; i < 2304; i += 256) {
            int idx = i * 4, m = idx / 96, kk = idx % 96;
            float4 v = *(const float4*)(w2 + m * 192 + kc * 96 + kk);
            float* d = ws + m * LDA + kk;
            d[0] = to_tf32(v.x); d[1] = to_tf32(v.y);
            d[2] = to_tf32(v.z); d[3] = to_tf32(v.w);
        }
        __syncthreads();
        gemm_t(ws, hs + kc * 96 * LDB, a2, wm, wn);
    }

    float* ob = out + (size_t)b * C_ * HW + p0;
    #pragma unroll
    for (int mf = 0; mf < 3; mf++)
        #pragma unroll
        for (int nf = 0; nf < 2; nf++) {
            wmma::store_matrix_sync(st, a2[mf][nf], 16, wmma::mem_row_major);
            __syncwarp();
            int mm = wm * 48 + mf * 16 + r;
            int pp = wn * 32 + nf * 16 + cc;
            float bb = b2s[mm];
            const float* sp = st + r * 16 + cc;
            const float* x1p = as + mm * LDB + pp;
            float* gp = ob + (size_t)mm * HW + pp;
            #pragma unroll
            for (int q = 0; q < 8; q++) gp[q] = sp[q] + bb + x1p[q];
            __syncwarp();
        }
}

// ---------------------------------------------------------------------------
extern "C" void kernel_launch(void* const* d_in, const int* in_sizes, int n_in,
                              void* d_out, int out_size)
{
    const float* x       = (const float*)d_in[0];
    const float* prompt  = (const float*)d_in[1];
    const float* sweights= (const float*)d_in[2];
    const float* ln_w    = (const float*)d_in[3];
    const float* ln_b    = (const float*)d_in[4];
    const float* e0_pw_w = (const float*)d_in[5];
    const float* e0_pw_b = (const float*)d_in[6];
    const float* e0_dw_w = (const float*)d_in[7];
    const float* e0_dw_b = (const float*)d_in[8];
    const float* e1_dw_w = (const float*)d_in[9];
    const float* e1_dw_b = (const float*)d_in[10];
    const float* e2_dw_w = (const float*)d_in[11];
    const float* e2_dw_b = (const float*)d_in[12];
    const float* proj_w  = (const float*)d_in[13];
    const float* proj_b  = (const float*)d_in[14];
    const float* ffn1_w  = (const float*)d_in[15];
    const float* ffn1_b  = (const float*)d_in[16];
    const float* ffn2_w  = (const float*)d_in[17];
    const float* ffn2_b  = (const float*)d_in[18];
    float* out = (float*)d_out;

    cudaFuncSetAttribute(k_ln_e0pw, cudaFuncAttributeMaxDynamicSharedMemorySize, LN_FLTS * 4);
    cudaFuncSetAttribute(k_projffn, cudaFuncAttributeMaxDynamicSharedMemorySize, PF_FLTS * 4);

    dim3 gg(HW / 128, B_);

    k_ln_e0pw<<<gg, 256, LN_FLTS * 4>>>(x, ln_w, ln_b, e0_pw_w, e0_pw_b);

    dim3 gdw((H_/TS) * (W_/TS), C_, B_);
    k_dw<<<gdw, 256>>>(sweights, prompt,
                       e0_dw_w, e0_dw_b, e1_dw_w, e1_dw_b, e2_dw_w, e2_dw_b);

    k_projffn<<<gg, 256, PF_FLTS * 4>>>(x, proj_w, proj_b,
                                        ffn1_w, ffn1_b, ffn2_w, ffn2_b, out);
}

// round 7
// speedup vs baseline: 1.1347x; 1.1347x over previous
#include <cuda_runtime.h>
#include <cuda_bf16.h>
#include <mma.h>
#include <math.h>
#include <stdint.h>

using namespace nvcuda;

#define B_ 4
#define C_ 96
#define H_ 256
#define W_ 256
#define HW (H_*W_)
#define LDA 104
#define LDB 136

typedef __nv_bfloat16 bf16;

// Scratch (allocation-free rule: __device__ globals)
__device__ float g_xn[B_*C_*HW];   // layernorm output
__device__ float g_e0[B_*C_*HW];   // e0 pointwise pre-activation
__device__ float g_xa[B_*C_*HW];   // x_adaptive
__device__ float g_x1[B_*C_*HW];   // proj output + residual

using FragA = wmma::fragment<wmma::matrix_a, 16, 16, 16, bf16, wmma::row_major>;
using FragB = wmma::fragment<wmma::matrix_b, 16, 16, 16, bf16, wmma::row_major>;
using FragC = wmma::fragment<wmma::accumulator, 16, 16, 16, float>;

__device__ __forceinline__ void split_bf16(float v, bf16& h, bf16& l) {
    h = __float2bfloat16_rn(v);
    l = __float2bfloat16_rn(v - __bfloat162float(h));
}

// Split-load a [96][96] f32 weight chunk (row stride rs) into smem bf16 hi/lo [96][LDA]
__device__ __forceinline__ void load_w(const float* __restrict__ src, int rs,
                                       bf16* wsh, bf16* wsl, int t, int nthr)
{
    for (int i = t; i < 2304; i += nthr) {
        int m = i / 24, kk = (i % 24) * 4;
        float4 v = *(const float4*)(src + m * rs + kk);
        bf16 h0,l0,h1,l1,h2,l2,h3,l3;
        split_bf16(v.x, h0, l0); split_bf16(v.y, h1, l1);
        split_bf16(v.z, h2, l2); split_bf16(v.w, h3, l3);
        __nv_bfloat162* dh = (__nv_bfloat162*)(wsh + m * LDA + kk);
        __nv_bfloat162* dl = (__nv_bfloat162*)(wsl + m * LDA + kk);
        dh[0] = __nv_bfloat162{h0, h1}; dh[1] = __nv_bfloat162{h2, h3};
        dl[0] = __nv_bfloat162{l0, l1}; dl[1] = __nv_bfloat162{l2, l3};
    }
}

// 3-pass GEMM, 256 threads (8 warps, 2x4 grid, 2 n-frags per warp)
__device__ __forceinline__ void gemm3_n32(
    const bf16* ah, const bf16* al, const bf16* bh, const bf16* bl,
    FragC (&acc)[3][2], int wm, int wn)
{
    #pragma unroll 1
    for (int k = 0; k < 6; k++) {
        FragB b_h[2], b_l[2];
        #pragma unroll
        for (int nf = 0; nf < 2; nf++) {
            wmma::load_matrix_sync(b_h[nf], bh + (k*16)*LDB + wn*32 + nf*16, LDB);
            wmma::load_matrix_sync(b_l[nf], bl + (k*16)*LDB + wn*32 + nf*16, LDB);
        }
        #pragma unroll
        for (int mf = 0; mf < 3; mf++) {
            FragA a_h, a_l;
            wmma::load_matrix_sync(a_h, ah + (wm*48 + mf*16)*LDA + k*16, LDA);
            wmma::load_matrix_sync(a_l, al + (wm*48 + mf*16)*LDA + k*16, LDA);
            #pragma unroll
            for (int nf = 0; nf < 2; nf++) {
                wmma::mma_sync(acc[mf][nf], a_h, b_h[nf], acc[mf][nf]);
                wmma::mma_sync(acc[mf][nf], a_h, b_l[nf], acc[mf][nf]);
                wmma::mma_sync(acc[mf][nf], a_l, b_h[nf], acc[mf][nf]);
            }
        }
    }
}

// 3-pass GEMM, 512 threads (16 warps, 2x8 grid, 1 n-frag per warp)
__device__ __forceinline__ void gemm3_n16(
    const bf16* ah, const bf16* al, const bf16* bh, const bf16* bl,
    FragC (&acc)[3], int wm, int wn)
{
    #pragma unroll 1
    for (int k = 0; k < 6; k++) {
        FragB b_h, b_l;
        wmma::load_matrix_sync(b_h, bh + (k*16)*LDB + wn*16, LDB);
        wmma::load_matrix_sync(b_l, bl + (k*16)*LDB + wn*16, LDB);
        #pragma unroll
        for (int mf = 0; mf < 3; mf++) {
            FragA a_h, a_l;
            wmma::load_matrix_sync(a_h, ah + (wm*48 + mf*16)*LDA + k*16, LDA);
            wmma::load_matrix_sync(a_l, al + (wm*48 + mf*16)*LDA + k*16, LDA);
            wmma::mma_sync(acc[mf], a_h, b_h, acc[mf]);
            wmma::mma_sync(acc[mf], a_h, b_l, acc[mf]);
            wmma::mma_sync(acc[mf], a_l, b_h, acc[mf]);
        }
    }
}

// ---------------------------------------------------------------------------
// Kernel 1: LayerNorm (stats via two-phase global read) + e0 pointwise
// smem 102.5KB -> 2 CTAs/SM
// ---------------------------------------------------------------------------
#define LN_XSH 0
#define LN_XSL 26112
#define LN_WSH 52224
#define LN_WSL 72192
#define LN_STG 92160
#define LN_MU  100352
#define LN_INV 100864
#define LN_LNW 101376
#define LN_LNB 101760
#define LN_BS  102144
#define LN_BYTES 102528

__global__ __launch_bounds__(256, 2) void k_ln_e0pw(
    const float* __restrict__ x,
    const float* __restrict__ lnw, const float* __restrict__ lnb,
    const float* __restrict__ w, const float* __restrict__ bias)
{
    extern __shared__ unsigned char smraw[];
    bf16* xsh = (bf16*)(smraw + LN_XSH);
    bf16* xsl = (bf16*)(smraw + LN_XSL);
    bf16* wsh = (bf16*)(smraw + LN_WSH);
    bf16* wsl = (bf16*)(smraw + LN_WSL);
    float* stg  = (float*)(smraw + LN_STG);
    float* mu   = (float*)(smraw + LN_MU);
    float* inv  = (float*)(smraw + LN_INV);
    float* lnws = (float*)(smraw + LN_LNW);
    float* lnbs = (float*)(smraw + LN_LNB);
    float* bs   = (float*)(smraw + LN_BS);

    const int t = threadIdx.x, wid = t >> 5, lane = t & 31;
    const int b = blockIdx.y, p0 = blockIdx.x * 128;
    const float* xb = x + (size_t)b * C_ * HW + p0;

    load_w(w, 96, wsh, wsl, t, 256);
    if (t < 96) { lnws[t] = lnw[t]; lnbs[t] = lnb[t]; bs[t] = bias[t]; }

    // stats pass: warp wid reads rows {wid, wid+8, ...}, lane covers 4 pixels
    const int c4 = lane * 4;
    float s0=0,s1=0,s2=0,s3=0, q0=0,q1=0,q2=0,q3=0;
    #pragma unroll 1
    for (int it = 0; it < 12; it++) {
        float4 v = *(const float4*)(xb + (size_t)(it * 8 + wid) * HW + c4);
        s0 += v.x; s1 += v.y; s2 += v.z; s3 += v.w;
        q0 += v.x*v.x; q1 += v.y*v.y; q2 += v.z*v.z; q3 += v.w*v.w;
    }
    float* psum = stg;          // [8][128]
    float* psq  = stg + 1024;   // [8][128]
    psum[wid*128 + c4 + 0] = s0; psum[wid*128 + c4 + 1] = s1;
    psum[wid*128 + c4 + 2] = s2; psum[wid*128 + c4 + 3] = s3;
    psq [wid*128 + c4 + 0] = q0; psq [wid*128 + c4 + 1] = q1;
    psq [wid*128 + c4 + 2] = q2; psq [wid*128 + c4 + 3] = q3;
    __syncthreads();

    if (t < 128) {
        float s = 0.f, q = 0.f;
        #pragma unroll
        for (int g = 0; g < 8; g++) { s += psum[g*128 + t]; q += psq[g*128 + t]; }
        float m = s * (1.f / 96.f);
        mu[t] = m;
        inv[t] = rsqrtf(q * (1.f / 96.f) - m * m + 1e-6f);
    }
    __syncthreads();

    // normalize (re-read x; L2-hot) + write xn + bf16 split to smem
    float* xnb = g_xn + (size_t)b * C_ * HW + p0;
    for (int i = t; i < 3072; i += 256) {
        int k = i >> 5, cc = (i & 31) * 4;
        float4 v = *(const float4*)(xb + (size_t)k * HW + cc);
        float lw = lnws[k], lb = lnbs[k];
        float o0 = (v.x - mu[cc+0]) * inv[cc+0] * lw + lb;
        float o1 = (v.y - mu[cc+1]) * inv[cc+1] * lw + lb;
        float o2 = (v.z - mu[cc+2]) * inv[cc+2] * lw + lb;
        float o3 = (v.w - mu[cc+3]) * inv[cc+3] * lw + lb;
        *(float4*)(xnb + (size_t)k * HW + cc) = make_float4(o0, o1, o2, o3);
        bf16 h0,l0,h1,l1,h2,l2,h3,l3;
        split_bf16(o0, h0, l0); split_bf16(o1, h1, l1);
        split_bf16(o2, h2, l2); split_bf16(o3, h3, l3);
        __nv_bfloat162* ph = (__nv_bfloat162*)(xsh + k * LDB + cc);
        __nv_bfloat162* pl = (__nv_bfloat162*)(xsl + k * LDB + cc);
        ph[0] = __nv_bfloat162{h0, h1}; ph[1] = __nv_bfloat162{h2, h3};
        pl[0] = __nv_bfloat162{l0, l1}; pl[1] = __nv_bfloat162{l2, l3};
    }
    __syncthreads();

    const int wm = wid >> 2, wn = wid & 3;
    FragC acc[3][2];
    #pragma unroll
    for (int mf = 0; mf < 3; mf++)
        #pragma unroll
        for (int nf = 0; nf < 2; nf++) wmma::fill_fragment(acc[mf][nf], 0.f);
    gemm3_n32(wsh, wsl, xsh, xsl, acc, wm, wn);

    float* st = stg + wid * 256;
    float* gb = g_e0 + (size_t)b * C_ * HW + p0;
    const int r = lane >> 1, c8 = (lane & 1) * 8;
    #pragma unroll
    for (int mf = 0; mf < 3; mf++)
        #pragma unroll
        for (int nf = 0; nf < 2; nf++) {
            wmma::store_matrix_sync(st, acc[mf][nf], 16, wmma::mem_row_major);
            __syncwarp();
            int mm = wm*48 + mf*16 + r;
            int pp = wn*32 + nf*16 + c8;
            float bb = bs[mm];
            float* gp = gb + (size_t)mm * HW + pp;
            const float* sp = st + r*16 + c8;
            #pragma unroll
            for (int q = 0; q < 8; q++) gp[q] = sp[q] + bb;
            __syncwarp();
        }
}

// ---------------------------------------------------------------------------
// Kernel 2: depthwise experts + mixing. 64x64 tiles, 8-px strips per thread.
// ---------------------------------------------------------------------------
__global__ __launch_bounds__(512, 2) void k_dw(
    const float* __restrict__ sw,
    const float* __restrict__ prompt,
    const float* __restrict__ w0, const float* __restrict__ b0,
    const float* __restrict__ w1, const float* __restrict__ b1,
    const float* __restrict__ w2, const float* __restrict__ b2)
{
    __shared__ float xs[76 * 77];
    __shared__ float es[66 * 67];
    __shared__ float kw[43];

    const int t = threadIdx.x;
    int c = blockIdx.y, b = blockIdx.z;
    int ty0 = (blockIdx.x >> 2) * 64;
    int tx0 = (blockIdx.x & 3) * 64;
    const float* xn = g_xn + ((size_t)(b * C_ + c)) * HW;
    const float* ep = g_e0 + ((size_t)(b * C_ + c)) * HW;

    for (int i = t; i < 76 * 76; i += 512) {
        int r = i / 76, cc = i % 76;
        int yy = ty0 - 6 + r, xx = tx0 - 6 + cc;
        xs[r * 77 + cc] = (yy >= 0 && yy < H_ && xx >= 0 && xx < W_) ? xn[yy * W_ + xx] : 0.f;
    }
    for (int i = t; i < 66 * 66; i += 512) {
        int r = i / 66, cc = i % 66;
        int yy = ty0 - 1 + r, xx = tx0 - 1 + cc;
        es[r * 67 + cc] = (yy >= 0 && yy < H_ && xx >= 0 && xx < W_) ? ep[yy * W_ + xx] : 0.f;
    }
    if (t < 43) {
        kw[t] = (t < 9) ? __ldg(&w0[c*9 + t])
              : (t < 18) ? __ldg(&w1[c*9 + t - 9])
              : __ldg(&w2[c*25 + t - 18]);
    }
    float bb0 = __ldg(&b0[c]), bb1 = __ldg(&b1[c]), bb2 = __ldg(&b2[c]);
    float s0 = __ldg(&sw[b*3+0]), s1 = __ldg(&sw[b*3+1]), s2 = __ldg(&sw[b*3+2]);
    float pm = 1.f + __ldg(&prompt[b * C_ + c]);
    __syncthreads();

    const int py = t >> 3, px0 = (t & 7) * 8;
    float o[8], r8[8];

    // e0: 3x3 dil1 on e0_pre
    #pragma unroll
    for (int j = 0; j < 8; j++) r8[j] = bb0;
    #pragma unroll
    for (int ky = 0; ky < 3; ky++)
        #pragma unroll
        for (int kx = 0; kx < 3; kx++) {
            float wv = kw[ky*3 + kx];
            const float* rowp = es + (py + ky) * 67 + px0 + kx;
            #pragma unroll
            for (int j = 0; j < 8; j++) r8[j] += wv * rowp[j];
        }
    #pragma unroll
    for (int j = 0; j < 8; j++) o[j] = s0 * r8[j];

    // e1: 3x3 dil2 on xn
    #pragma unroll
    for (int j = 0; j < 8; j++) r8[j] = bb1;
    #pragma unroll
    for (int ky = 0; ky < 3; ky++)
        #pragma unroll
        for (int kx = 0; kx < 3; kx++) {
            float wv = kw[9 + ky*3 + kx];
            const float* rowp = xs + (py + 4 + 2*ky) * 77 + px0 + 4 + 2*kx;
            #pragma unroll
            for (int j = 0; j < 8; j++) r8[j] += wv * rowp[j];
        }
    #pragma unroll
    for (int j = 0; j < 8; j++) o[j] += s1 * r8[j];

    // e2: 5x5 dil3 on xn
    #pragma unroll
    for (int j = 0; j < 8; j++) r8[j] = bb2;
    #pragma unroll
    for (int ky = 0; ky < 5; ky++)
        #pragma unroll
        for (int kx = 0; kx < 5; kx++) {
            float wv = kw[18 + ky*5 + kx];
            const float* rowp = xs + (py + 3*ky) * 77 + px0 + 3*kx;
            #pragma unroll
            for (int j = 0; j < 8; j++) r8[j] += wv * rowp[j];
        }
    #pragma unroll
    for (int j = 0; j < 8; j++) o[j] = (o[j] + s2 * r8[j]) * pm;

    float* outp = g_xa + ((size_t)(b * C_ + c)) * HW + (ty0 + py) * W_ + tx0 + px0;
    *(float4*)(outp)     = make_float4(o[0], o[1], o[2], o[3]);
    *(float4*)(outp + 4) = make_float4(o[4], o[5], o[6], o[7]);
}

// ---------------------------------------------------------------------------
// Kernel 3: x1 = x + proj(xa) -> g_x1. 512 threads, 2 CTAs/SM.
// ---------------------------------------------------------------------------
#define PJ_XSH 0
#define PJ_XSL 26112
#define PJ_WSH 52224
#define PJ_WSL 72192
#define PJ_STG 92160
#define PJ_BS  108544
#define PJ_BYTES 108928

__global__ __launch_bounds__(512, 2) void k_proj(
    const float* __restrict__ x,
    const float* __restrict__ w, const float* __restrict__ bias)
{
    extern __shared__ unsigned char smraw[];
    bf16* xsh = (bf16*)(smraw + PJ_XSH);
    bf16* xsl = (bf16*)(smraw + PJ_XSL);
    bf16* wsh = (bf16*)(smraw + PJ_WSH);
    bf16* wsl = (bf16*)(smraw + PJ_WSL);
    float* stg = (float*)(smraw + PJ_STG);
    float* bs  = (float*)(smraw + PJ_BS);

    const int t = threadIdx.x, wid = t >> 5, lane = t & 31;
    const int b = blockIdx.y, p0 = blockIdx.x * 128;
    const float* ab = g_xa + (size_t)b * C_ * HW + p0;

    for (int i = t; i < 3072; i += 512) {
        int k = i >> 5, cc = (i & 31) * 4;
        float4 v = *(const float4*)(ab + (size_t)k * HW + cc);
        bf16 h0,l0,h1,l1,h2,l2,h3,l3;
        split_bf16(v.x, h0, l0); split_bf16(v.y, h1, l1);
        split_bf16(v.z, h2, l2); split_bf16(v.w, h3, l3);
        __nv_bfloat162* ph = (__nv_bfloat162*)(xsh + k * LDB + cc);
        __nv_bfloat162* pl = (__nv_bfloat162*)(xsl + k * LDB + cc);
        ph[0] = __nv_bfloat162{h0, h1}; ph[1] = __nv_bfloat162{h2, h3};
        pl[0] = __nv_bfloat162{l0, l1}; pl[1] = __nv_bfloat162{l2, l3};
    }
    load_w(w, 96, wsh, wsl, t, 512);
    if (t < 96) bs[t] = bias[t];
    __syncthreads();

    const int wm = wid >> 3, wn = wid & 7;
    FragC acc[3];
    #pragma unroll
    for (int mf = 0; mf < 3; mf++) wmma::fill_fragment(acc[mf], 0.f);
    gemm3_n16(wsh, wsl, xsh, xsl, acc, wm, wn);

    float* st = stg + wid * 256;
    const float* rb = x   + (size_t)b * C_ * HW + p0;
    float* gb = g_x1 + (size_t)b * C_ * HW + p0;
    const int r = lane >> 1, c8 = (lane & 1) * 8;
    #pragma unroll
    for (int mf = 0; mf < 3; mf++) {
        wmma::store_matrix_sync(st, acc[mf], 16, wmma::mem_row_major);
        __syncwarp();
        int mm = wm*48 + mf*16 + r;
        int pp = wn*16 + c8;
        float bb = bs[mm];
        const float* rp = rb + (size_t)mm * HW + pp;
        const float* sp = st + r*16 + c8;
        float* gp = gb + (size_t)mm * HW + pp;
        #pragma unroll
        for (int q = 0; q < 8; q++) gp[q] = sp[q] + bb + rp[q];
        __syncwarp();
    }
}

// ---------------------------------------------------------------------------
// Kernel 4: out = x1 + ffn2(gelu(ffn1(x1))). 512 threads, h in smem bf16 hi/lo.
// Residual reconstructed from in-smem x1 split (no global re-read).
// ---------------------------------------------------------------------------
#define FF_XSH 0
#define FF_XSL 26112
#define FF_HSH 52224
#define FF_HSL 104448
#define FF_WSH 156672
#define FF_WSL 176640
#define FF_STG 196608
#define FF_B1  212992
#define FF_B2  213760
#define FF_BYTES 214144

__global__ __launch_bounds__(512, 1) void k_ffn(
    const float* __restrict__ w1, const float* __restrict__ b1v,
    const float* __restrict__ w2, const float* __restrict__ b2v,
    float* __restrict__ out)
{
    extern __shared__ unsigned char smraw[];
    bf16* xsh = (bf16*)(smraw + FF_XSH);
    bf16* xsl = (bf16*)(smraw + FF_XSL);
    bf16* hsh = (bf16*)(smraw + FF_HSH);
    bf16* hsl = (bf16*)(smraw + FF_HSL);
    bf16* wsh = (bf16*)(smraw + FF_WSH);
    bf16* wsl = (bf16*)(smraw + FF_WSL);
    float* stg = (float*)(smraw + FF_STG);
    float* b1s = (float*)(smraw + FF_B1);
    float* b2s = (float*)(smraw + FF_B2);

    const int t = threadIdx.x, wid = t >> 5, lane = t & 31;
    const int b = blockIdx.y, p0 = blockIdx.x * 128;
    const float* x1b = g_x1 + (size_t)b * C_ * HW + p0;

    for (int i = t; i < 3072; i += 512) {
        int k = i >> 5, cc = (i & 31) * 4;
        float4 v = *(const float4*)(x1b + (size_t)k * HW + cc);
        bf16 h0,l0,h1,l1,h2,l2,h3,l3;
        split_bf16(v.x, h0, l0); split_bf16(v.y, h1, l1);
        split_bf16(v.z, h2, l2); split_bf16(v.w, h3, l3);
        __nv_bfloat162* ph = (__nv_bfloat162*)(xsh + k * LDB + cc);
        __nv_bfloat162* pl = (__nv_bfloat162*)(xsl + k * LDB + cc);
        ph[0] = __nv_bfloat162{h0, h1}; ph[1] = __nv_bfloat162{h2, h3};
        pl[0] = __nv_bfloat162{l0, l1}; pl[1] = __nv_bfloat162{l2, l3};
    }
    load_w(w1, 96, wsh, wsl, t, 512);   // w1 chunk 0
    if (t < 192) b1s[t] = b1v[t];
    if (t < 96)  b2s[t] = b2v[t];
    __syncthreads();

    const int wm = wid >> 3, wn = wid & 7;
    const int r = lane >> 1, c8 = (lane & 1) * 8;
    float* st = stg + wid * 256;

    // ---- GEMM1: h = gelu(w1 @ x1 + b1), two 96-row chunks ----
    #pragma unroll 1
    for (int oc = 0; oc < 2; oc++) {
        if (oc == 1) {
            __syncthreads();                    // GEMM c0 readers done
            load_w(w1 + 9216, 96, wsh, wsl, t, 512);
            __syncthreads();
        }
        FragC a1[3];
        #pragma unroll
        for (int mf = 0; mf < 3; mf++) wmma::fill_fragment(a1[mf], 0.f);
        gemm3_n16(wsh, wsl, xsh, xsl, a1, wm, wn);

        #pragma unroll
        for (int mf = 0; mf < 3; mf++) {
            wmma::store_matrix_sync(st, a1[mf], 16, wmma::mem_row_major);
            __syncwarp();
            int k2 = oc*96 + wm*48 + mf*16 + r;
            int pp = wn*16 + c8;
            float bb = b1s[k2];
            const float* sp = st + r*16 + c8;
            bf16* dh = hsh + k2 * LDB + pp;
            bf16* dl = hsl + k2 * LDB + pp;
            #pragma unroll
            for (int q = 0; q < 8; q++) {
                float hv = sp[q] + bb;
                float gv = hv * normcdff(hv);
                bf16 hh, ll; split_bf16(gv, hh, ll);
                dh[q] = hh; dl[q] = ll;
            }
            __syncwarp();
        }
    }

    // ---- GEMM2: acc2 = w2 @ h, K=192 in two chunks ----
    FragC a2[3];
    #pragma unroll
    for (int mf = 0; mf < 3; mf++) wmma::fill_fragment(a2[mf], 0.f);
    #pragma unroll 1
    for (int kc = 0; kc < 2; kc++) {
        __syncthreads();                        // hs complete / ws readers done
        load_w(w2 + kc * 96, 192, wsh, wsl, t, 512);
        __syncthreads();
        gemm3_n16(wsh, wsl, hsh + kc * 96 * LDB, hsl + kc * 96 * LDB, a2, wm, wn);
    }

    // ---- Epilogue: out = x1 (from smem split) + acc2 + b2 ----
    float* ob = out + (size_t)b * C_ * HW + p0;
    #pragma unroll
    for (int mf = 0; mf < 3; mf++) {
        wmma::store_matrix_sync(st, a2[mf], 16, wmma::mem_row_major);
        __syncwarp();
        int mm = wm*48 + mf*16 + r;
        int pp = wn*16 + c8;
        float bb = b2s[mm];
        const float* sp = st + r*16 + c8;
        const bf16* xh = xsh + mm * LDB + pp;
        const bf16* xl = xsl + mm * LDB + pp;
        float* gp = ob + (size_t)mm * HW + pp;
        #pragma unroll
        for (int q = 0; q < 8; q++) {
            float x1v = __bfloat162float(xh[q]) + __bfloat162float(xl[q]);
            gp[q] = sp[q] + bb + x1v;
        }
        __syncwarp();
    }
}

// ---------------------------------------------------------------------------
extern "C" void kernel_launch(void* const* d_in, const int* in_sizes, int n_in,
                              void* d_out, int out_size)
{
    const float* x       = (const float*)d_in[0];
    const float* prompt  = (const float*)d_in[1];
    const float* sweights= (const float*)d_in[2];
    const float* ln_w    = (const float*)d_in[3];
    const float* ln_b    = (const float*)d_in[4];
    const float* e0_pw_w = (const float*)d_in[5];
    const float* e0_pw_b = (const float*)d_in[6];
    const float* e0_dw_w = (const float*)d_in[7];
    const float* e0_dw_b = (const float*)d_in[8];
    const float* e1_dw_w = (const float*)d_in[9];
    const float* e1_dw_b = (const float*)d_in[10];
    const float* e2_dw_w = (const float*)d_in[11];
    const float* e2_dw_b = (const float*)d_in[12];
    const float* proj_w  = (const float*)d_in[13];
    const float* proj_b  = (const float*)d_in[14];
    const float* ffn1_w  = (const float*)d_in[15];
    const float* ffn1_b  = (const float*)d_in[16];
    const float* ffn2_w  = (const float*)d_in[17];
    const float* ffn2_b  = (const float*)d_in[18];
    float* out = (float*)d_out;

    cudaFuncSetAttribute(k_ln_e0pw, cudaFuncAttributeMaxDynamicSharedMemorySize, LN_BYTES);
    cudaFuncSetAttribute(k_proj,    cudaFuncAttributeMaxDynamicSharedMemorySize, PJ_BYTES);
    cudaFuncSetAttribute(k_ffn,     cudaFuncAttributeMaxDynamicSharedMemorySize, FF_BYTES);

    dim3 gg(HW / 128, B_);

    k_ln_e0pw<<<gg, 256, LN_BYTES>>>(x, ln_w, ln_b, e0_pw_w, e0_pw_b);

    dim3 gdw(16, C_, B_);
    k_dw<<<gdw, 512>>>(sweights, prompt,
                       e0_dw_w, e0_dw_b, e1_dw_w, e1_dw_b, e2_dw_w, e2_dw_b);

    k_proj<<<gg, 512, PJ_BYTES>>>(x, proj_w, proj_b);

    k_ffn<<<gg, 512, FF_BYTES>>>(ffn1_w, ffn1_b, ffn2_w, ffn2_b, out);
}

// round 8
// speedup vs baseline: 1.5589x; 1.3738x over previous
#include <cuda_runtime.h>
#include <cuda_bf16.h>
#include <mma.h>
#include <math.h>
#include <stdint.h>

using namespace nvcuda;

#define B_ 4
#define C_ 96
#define H_ 256
#define W_ 256
#define HW (H_*W_)
#define LDA 104
#define LDW 72        // 64-px tile B row stride (bf16)

typedef __nv_bfloat16 bf16;

// Scratch (allocation-free rule: __device__ globals)
__device__ float g_xn[B_*C_*HW];
__device__ float g_e0[B_*C_*HW];
__device__ float g_xa[B_*C_*HW];
__device__ float g_x1[B_*C_*HW];
__device__ float g_h [B_*192*HW];

using FragA = wmma::fragment<wmma::matrix_a, 16, 16, 16, bf16, wmma::row_major>;
using FragB = wmma::fragment<wmma::matrix_b, 16, 16, 16, bf16, wmma::row_major>;
using FragC = wmma::fragment<wmma::accumulator, 16, 16, 16, float>;

__device__ __forceinline__ void split_bf16(float v, bf16& h, bf16& l) {
    h = __float2bfloat16_rn(v);
    l = __float2bfloat16_rn(v - __bfloat162float(h));
}

// Split-load a [96][96] f32 weight chunk (row stride rs) into smem bf16 hi/lo [96][LDA]
__device__ __forceinline__ void load_w(const float* __restrict__ src, int rs,
                                       bf16* wsh, bf16* wsl, int t)
{
    for (int i = t; i < 2304; i += 256) {
        int m = i / 24, kk = (i % 24) * 4;
        float4 v = *(const float4*)(src + m * rs + kk);
        bf16 h0,l0,h1,l1,h2,l2,h3,l3;
        split_bf16(v.x, h0, l0); split_bf16(v.y, h1, l1);
        split_bf16(v.z, h2, l2); split_bf16(v.w, h3, l3);
        __nv_bfloat162* dh = (__nv_bfloat162*)(wsh + m * LDA + kk);
        __nv_bfloat162* dl = (__nv_bfloat162*)(wsl + m * LDA + kk);
        dh[0] = __nv_bfloat162{h0, h1}; dh[1] = __nv_bfloat162{h2, h3};
        dl[0] = __nv_bfloat162{l0, l1}; dl[1] = __nv_bfloat162{l2, l3};
    }
}

// Split-load activations tile [96 ch][64 px] (f32, row stride HW) -> smem [96][LDW]
__device__ __forceinline__ void load_act(const float* __restrict__ src,
                                         bf16* xh, bf16* xl, int t)
{
    for (int i = t; i < 1536; i += 256) {     // 96*16 float4
        int k = i >> 4, cc = (i & 15) * 4;
        float4 v = *(const float4*)(src + (size_t)k * HW + cc);
        bf16 h0,l0,h1,l1,h2,l2,h3,l3;
        split_bf16(v.x, h0, l0); split_bf16(v.y, h1, l1);
        split_bf16(v.z, h2, l2); split_bf16(v.w, h3, l3);
        __nv_bfloat162* ph = (__nv_bfloat162*)(xh + k * LDW + cc);
        __nv_bfloat162* pl = (__nv_bfloat162*)(xl + k * LDW + cc);
        ph[0] = __nv_bfloat162{h0, h1}; ph[1] = __nv_bfloat162{h2, h3};
        pl[0] = __nv_bfloat162{l0, l1}; pl[1] = __nv_bfloat162{l2, l3};
    }
}

// 3-pass GEMM: C[96 x 64] += A[96x96] * B[96x64]. 8 warps: wm 0..1, wn 0..3.
__device__ __forceinline__ void gemm3(
    const bf16* ah, const bf16* al, const bf16* bh, const bf16* bl,
    FragC (&acc)[3], int wm, int wn)
{
    #pragma unroll 1
    for (int k = 0; k < 6; k++) {
        FragB b_h, b_l;
        wmma::load_matrix_sync(b_h, bh + (k*16)*LDW + wn*16, LDW);
        wmma::load_matrix_sync(b_l, bl + (k*16)*LDW + wn*16, LDW);
        #pragma unroll
        for (int mf = 0; mf < 3; mf++) {
            FragA a_h, a_l;
            wmma::load_matrix_sync(a_h, ah + (wm*48 + mf*16)*LDA + k*16, LDA);
            wmma::load_matrix_sync(a_l, al + (wm*48 + mf*16)*LDA + k*16, LDA);
            wmma::mma_sync(acc[mf], a_h, b_h, acc[mf]);
            wmma::mma_sync(acc[mf], a_h, b_l, acc[mf]);
            wmma::mma_sync(acc[mf], a_l, b_h, acc[mf]);
        }
    }
}

__device__ __forceinline__ void zero3(FragC (&acc)[3]) {
    #pragma unroll
    for (int mf = 0; mf < 3; mf++) wmma::fill_fragment(acc[mf], 0.f);
}

// ---------------------------------------------------------------------------
// smem layout (bytes), shared by all GEMM kernels:
//   XSH 0, XSL 13824, WSH 27648 (stg aliases here), WSL 47616, params 67584+
// ---------------------------------------------------------------------------
#define S_XSH 0
#define S_XSL 13824
#define S_WSH 27648
#define S_WSL 47616
#define S_PRM 67584
#define S_END (S_PRM + 4608)   // params/stats region

// ---------------------------------------------------------------------------
// Kernel 1: LayerNorm (2-phase global read) + e0 pointwise -> g_xn, g_e0
// ---------------------------------------------------------------------------
__global__ __launch_bounds__(256, 3) void k_ln_e0pw(
    const float* __restrict__ x,
    const float* __restrict__ lnw, const float* __restrict__ lnb,
    const float* __restrict__ w, const float* __restrict__ bias)
{
    extern __shared__ unsigned char smraw[];
    bf16* xsh = (bf16*)(smraw + S_XSH);
    bf16* xsl = (bf16*)(smraw + S_XSL);
    bf16* wsh = (bf16*)(smraw + S_WSH);
    bf16* wsl = (bf16*)(smraw + S_WSL);
    float* stg = (float*)(smraw + S_WSH);        // aliases WSH after GEMM
    float* prm = (float*)(smraw + S_PRM);
    float* psum = prm;           // [8][64]
    float* psq  = prm + 512;     // [8][64]
    float* mu   = prm + 512;     // aliases psq after reduce? NO - keep separate
    // layout: psum[0..511], psq[512..1023], mu[1024..1087], inv[1088..1151]
    float* inv;
    mu  = prm + 1024;
    inv = prm + 1088;
    // params appended after psq region is done being used? keep simple: no alias

    const int t = threadIdx.x, wid = t >> 5, lane = t & 31;
    const int b = blockIdx.y, p0 = blockIdx.x * 64;
    const float* xb = x + (size_t)b * C_ * HW + p0;

    load_w(w, 96, wsh, wsl, t);

    // stats: warp wid covers rows {wid, wid+8,...}, lane covers 2 px
    {
        const int c2 = lane * 2;
        float s0=0, s1=0, q0=0, q1=0;
        #pragma unroll 1
        for (int it = 0; it < 12; it++) {
            float2 v = *(const float2*)(xb + (size_t)(it * 8 + wid) * HW + c2);
            s0 += v.x; s1 += v.y; q0 += v.x*v.x; q1 += v.y*v.y;
        }
        psum[wid*64 + c2] = s0; psum[wid*64 + c2 + 1] = s1;
        psq [wid*64 + c2] = q0; psq [wid*64 + c2 + 1] = q1;
    }
    __syncthreads();
    if (t < 64) {
        float s = 0.f, q = 0.f;
        #pragma unroll
        for (int g = 0; g < 8; g++) { s += psum[g*64 + t]; q += psq[g*64 + t]; }
        float m = s * (1.f / 96.f);
        mu[t] = m;
        inv[t] = rsqrtf(q * (1.f / 96.f) - m * m + 1e-6f);
    }
    __syncthreads();

    // normalize (L2-hot re-read) + write xn + split into smem
    float* xnb = g_xn + (size_t)b * C_ * HW + p0;
    for (int i = t; i < 1536; i += 256) {
        int k = i >> 4, cc = (i & 15) * 4;
        float4 v = *(const float4*)(xb + (size_t)k * HW + cc);
        float lw = __ldg(&lnw[k]), lb = __ldg(&lnb[k]);
        float o0 = (v.x - mu[cc+0]) * inv[cc+0] * lw + lb;
        float o1 = (v.y - mu[cc+1]) * inv[cc+1] * lw + lb;
        float o2 = (v.z - mu[cc+2]) * inv[cc+2] * lw + lb;
        float o3 = (v.w - mu[cc+3]) * inv[cc+3] * lw + lb;
        *(float4*)(xnb + (size_t)k * HW + cc) = make_float4(o0, o1, o2, o3);
        bf16 h0,l0,h1,l1,h2,l2,h3,l3;
        split_bf16(o0, h0, l0); split_bf16(o1, h1, l1);
        split_bf16(o2, h2, l2); split_bf16(o3, h3, l3);
        __nv_bfloat162* ph = (__nv_bfloat162*)(xsh + k * LDW + cc);
        __nv_bfloat162* pl = (__nv_bfloat162*)(xsl + k * LDW + cc);
        ph[0] = __nv_bfloat162{h0, h1}; ph[1] = __nv_bfloat162{h2, h3};
        pl[0] = __nv_bfloat162{l0, l1}; pl[1] = __nv_bfloat162{l2, l3};
    }
    __syncthreads();

    const int wm = wid >> 2, wn = wid & 3;
    FragC acc[3];
    zero3(acc);
    gemm3(wsh, wsl, xsh, xsl, acc, wm, wn);
    __syncthreads();                 // ws dead -> stg alias safe

    float* st = stg + wid * 256;
    float* gb = g_e0 + (size_t)b * C_ * HW + p0;
    const int r = lane >> 1, c8 = (lane & 1) * 8;
    #pragma unroll
    for (int mf = 0; mf < 3; mf++) {
        wmma::store_matrix_sync(st, acc[mf], 16, wmma::mem_row_major);
        __syncwarp();
        int mm = wm*48 + mf*16 + r;
        int pp = wn*16 + c8;
        float bb = __ldg(&bias[mm]);
        float* gp = gb + (size_t)mm * HW + pp;
        const float* sp = st + r*16 + c8;
        #pragma unroll
        for (int q = 0; q < 8; q++) gp[q] = sp[q] + bb;
        __syncwarp();
    }
}

// ---------------------------------------------------------------------------
// Kernel 2: depthwise experts + mixing (64x64 tiles, 512 thr)
// ---------------------------------------------------------------------------
__global__ __launch_bounds__(512, 2) void k_dw(
    const float* __restrict__ sw,
    const float* __restrict__ prompt,
    const float* __restrict__ w0, const float* __restrict__ b0,
    const float* __restrict__ w1, const float* __restrict__ b1,
    const float* __restrict__ w2, const float* __restrict__ b2)
{
    __shared__ float xs[76 * 77];
    __shared__ float es[66 * 67];
    __shared__ float kw[43];

    const int t = threadIdx.x;
    int c = blockIdx.y, b = blockIdx.z;
    int ty0 = (blockIdx.x >> 2) * 64;
    int tx0 = (blockIdx.x & 3) * 64;
    const float* xn = g_xn + ((size_t)(b * C_ + c)) * HW;
    const float* ep = g_e0 + ((size_t)(b * C_ + c)) * HW;

    for (int i = t; i < 76 * 76; i += 512) {
        int r = i / 76, cc = i % 76;
        int yy = ty0 - 6 + r, xx = tx0 - 6 + cc;
        xs[r * 77 + cc] = (yy >= 0 && yy < H_ && xx >= 0 && xx < W_) ? xn[yy * W_ + xx] : 0.f;
    }
    for (int i = t; i < 66 * 66; i += 512) {
        int r = i / 66, cc = i % 66;
        int yy = ty0 - 1 + r, xx = tx0 - 1 + cc;
        es[r * 67 + cc] = (yy >= 0 && yy < H_ && xx >= 0 && xx < W_) ? ep[yy * W_ + xx] : 0.f;
    }
    if (t < 43) {
        kw[t] = (t < 9) ? __ldg(&w0[c*9 + t])
              : (t < 18) ? __ldg(&w1[c*9 + t - 9])
              : __ldg(&w2[c*25 + t - 18]);
    }
    float bb0 = __ldg(&b0[c]), bb1 = __ldg(&b1[c]), bb2 = __ldg(&b2[c]);
    float s0 = __ldg(&sw[b*3+0]), s1 = __ldg(&sw[b*3+1]), s2 = __ldg(&sw[b*3+2]);
    float pm = 1.f + __ldg(&prompt[b * C_ + c]);
    __syncthreads();

    const int py = t >> 3, px0 = (t & 7) * 8;
    float o[8], r8[8];

    #pragma unroll
    for (int j = 0; j < 8; j++) r8[j] = bb0;
    #pragma unroll
    for (int ky = 0; ky < 3; ky++)
        #pragma unroll
        for (int kx = 0; kx < 3; kx++) {
            float wv = kw[ky*3 + kx];
            const float* rowp = es + (py + ky) * 67 + px0 + kx;
            #pragma unroll
            for (int j = 0; j < 8; j++) r8[j] += wv * rowp[j];
        }
    #pragma unroll
    for (int j = 0; j < 8; j++) o[j] = s0 * r8[j];

    #pragma unroll
    for (int j = 0; j < 8; j++) r8[j] = bb1;
    #pragma unroll
    for (int ky = 0; ky < 3; ky++)
        #pragma unroll
        for (int kx = 0; kx < 3; kx++) {
            float wv = kw[9 + ky*3 + kx];
            const float* rowp = xs + (py + 4 + 2*ky) * 77 + px0 + 4 + 2*kx;
            #pragma unroll
            for (int j = 0; j < 8; j++) r8[j] += wv * rowp[j];
        }
    #pragma unroll
    for (int j = 0; j < 8; j++) o[j] += s1 * r8[j];

    #pragma unroll
    for (int j = 0; j < 8; j++) r8[j] = bb2;
    #pragma unroll
    for (int ky = 0; ky < 5; ky++)
        #pragma unroll
        for (int kx = 0; kx < 5; kx++) {
            float wv = kw[18 + ky*5 + kx];
            const float* rowp = xs + (py + 3*ky) * 77 + px0 + 3*kx;
            #pragma unroll
            for (int j = 0; j < 8; j++) r8[j] += wv * rowp[j];
        }
    #pragma unroll
    for (int j = 0; j < 8; j++) o[j] = (o[j] + s2 * r8[j]) * pm;

    float* outp = g_xa + ((size_t)(b * C_ + c)) * HW + (ty0 + py) * W_ + tx0 + px0;
    *(float4*)(outp)     = make_float4(o[0], o[1], o[2], o[3]);
    *(float4*)(outp + 4) = make_float4(o[4], o[5], o[6], o[7]);
}

// ---------------------------------------------------------------------------
// Kernel 3: x1 = x + proj(xa) -> g_x1
// ---------------------------------------------------------------------------
__global__ __launch_bounds__(256, 3) void k_proj(
    const float* __restrict__ x,
    const float* __restrict__ w, const float* __restrict__ bias)
{
    extern __shared__ unsigned char smraw[];
    bf16* xsh = (bf16*)(smraw + S_XSH);
    bf16* xsl = (bf16*)(smraw + S_XSL);
    bf16* wsh = (bf16*)(smraw + S_WSH);
    bf16* wsl = (bf16*)(smraw + S_WSL);
    float* stg = (float*)(smraw + S_WSH);

    const int t = threadIdx.x, wid = t >> 5, lane = t & 31;
    const int b = blockIdx.y, p0 = blockIdx.x * 64;

    load_act(g_xa + (size_t)b * C_ * HW + p0, xsh, xsl, t);
    load_w(w, 96, wsh, wsl, t);
    __syncthreads();

    const int wm = wid >> 2, wn = wid & 3;
    FragC acc[3];
    zero3(acc);
    gemm3(wsh, wsl, xsh, xsl, acc, wm, wn);
    __syncthreads();

    float* st = stg + wid * 256;
    const float* rb = x   + (size_t)b * C_ * HW + p0;
    float* gb = g_x1 + (size_t)b * C_ * HW + p0;
    const int r = lane >> 1, c8 = (lane & 1) * 8;
    #pragma unroll
    for (int mf = 0; mf < 3; mf++) {
        wmma::store_matrix_sync(st, acc[mf], 16, wmma::mem_row_major);
        __syncwarp();
        int mm = wm*48 + mf*16 + r;
        int pp = wn*16 + c8;
        float bb = __ldg(&bias[mm]);
        const float* rp = rb + (size_t)mm * HW + pp;
        const float* sp = st + r*16 + c8;
        float* gp = gb + (size_t)mm * HW + pp;
        #pragma unroll
        for (int q = 0; q < 8; q++) gp[q] = sp[q] + bb + rp[q];
        __syncwarp();
    }
}

// ---------------------------------------------------------------------------
// Kernel 4: h = gelu(ffn1(x1) + b1) -> g_h  (192 channels, two chunks)
// ---------------------------------------------------------------------------
__global__ __launch_bounds__(256, 3) void k_ffn1(
    const float* __restrict__ w1, const float* __restrict__ b1v)
{
    extern __shared__ unsigned char smraw[];
    bf16* xsh = (bf16*)(smraw + S_XSH);
    bf16* xsl = (bf16*)(smraw + S_XSL);
    bf16* wsh = (bf16*)(smraw + S_WSH);
    bf16* wsl = (bf16*)(smraw + S_WSL);
    float* stg = (float*)(smraw + S_WSH);

    const int t = threadIdx.x, wid = t >> 5, lane = t & 31;
    const int b = blockIdx.y, p0 = blockIdx.x * 64;

    load_act(g_x1 + (size_t)b * C_ * HW + p0, xsh, xsl, t);

    const int wm = wid >> 2, wn = wid & 3;
    const int r = lane >> 1, c8 = (lane & 1) * 8;
    float* st = stg + wid * 256;
    float* hb = g_h + (size_t)b * 192 * HW + p0;

    #pragma unroll 1
    for (int oc = 0; oc < 2; oc++) {
        __syncthreads();                       // xs ready / stg readers done
        load_w(w1 + oc * 9216, 96, wsh, wsl, t);
        __syncthreads();

        FragC acc[3];
        zero3(acc);
        gemm3(wsh, wsl, xsh, xsl, acc, wm, wn);
        __syncthreads();                       // ws dead -> stg alias

        #pragma unroll
        for (int mf = 0; mf < 3; mf++) {
            wmma::store_matrix_sync(st, acc[mf], 16, wmma::mem_row_major);
            __syncwarp();
            int k2 = oc*96 + wm*48 + mf*16 + r;
            int pp = wn*16 + c8;
            float bb = __ldg(&b1v[k2]);
            const float* sp = st + r*16 + c8;
            float* gp = hb + (size_t)k2 * HW + pp;
            #pragma unroll
            for (int q = 0; q < 8; q++) {
                float hv = sp[q] + bb;
                gp[q] = hv * normcdff(hv);
            }
            __syncwarp();
        }
    }
}

// ---------------------------------------------------------------------------
// Kernel 5: out = x1 + ffn2(h) + b2   (K=192 in two chunks)
// ---------------------------------------------------------------------------
__global__ __launch_bounds__(256, 3) void k_ffn2(
    const float* __restrict__ w2, const float* __restrict__ b2v,
    float* __restrict__ out)
{
    extern __shared__ unsigned char smraw[];
    bf16* hsh = (bf16*)(smraw + S_XSH);
    bf16* hsl = (bf16*)(smraw + S_XSL);
    bf16* wsh = (bf16*)(smraw + S_WSH);
    bf16* wsl = (bf16*)(smraw + S_WSL);
    float* stg = (float*)(smraw + S_WSH);

    const int t = threadIdx.x, wid = t >> 5, lane = t & 31;
    const int b = blockIdx.y, p0 = blockIdx.x * 64;
    const float* hb = g_h + (size_t)b * 192 * HW + p0;

    const int wm = wid >> 2, wn = wid & 3;
    FragC acc[3];
    zero3(acc);

    #pragma unroll 1
    for (int kc = 0; kc < 2; kc++) {
        if (kc) __syncthreads();               // prior readers done
        load_act(hb + (size_t)kc * 96 * HW, hsh, hsl, t);
        load_w(w2 + kc * 96, 192, wsh, wsl, t);
        __syncthreads();
        gemm3(wsh, wsl, hsh, hsl, acc, wm, wn);
    }
    __syncthreads();                           // ws dead -> stg alias

    float* st = stg + wid * 256;
    const float* x1b = g_x1 + (size_t)b * C_ * HW + p0;
    float* ob = out + (size_t)b * C_ * HW + p0;
    const int r = lane >> 1, c8 = (lane & 1) * 8;
    #pragma unroll
    for (int mf = 0; mf < 3; mf++) {
        wmma::store_matrix_sync(st, acc[mf], 16, wmma::mem_row_major);
        __syncwarp();
        int mm = wm*48 + mf*16 + r;
        int pp = wn*16 + c8;
        float bb = __ldg(&b2v[mm]);
        const float* sp = st + r*16 + c8;
        const float* rp = x1b + (size_t)mm * HW + pp;
        float* gp = ob + (size_t)mm * HW + pp;
        #pragma unroll
        for (int q = 0; q < 8; q++) gp[q] = sp[q] + bb + rp[q];
        __syncwarp();
    }
}

// ---------------------------------------------------------------------------
extern "C" void kernel_launch(void* const* d_in, const int* in_sizes, int n_in,
                              void* d_out, int out_size)
{
    const float* x       = (const float*)d_in[0];
    const float* prompt  = (const float*)d_in[1];
    const float* sweights= (const float*)d_in[2];
    const float* ln_w    = (const float*)d_in[3];
    const float* ln_b    = (const float*)d_in[4];
    const float* e0_pw_w = (const float*)d_in[5];
    const float* e0_pw_b = (const float*)d_in[6];
    const float* e0_dw_w = (const float*)d_in[7];
    const float* e0_dw_b = (const float*)d_in[8];
    const float* e1_dw_w = (const float*)d_in[9];
    const float* e1_dw_b = (const float*)d_in[10];
    const float* e2_dw_w = (const float*)d_in[11];
    const float* e2_dw_b = (const float*)d_in[12];
    const float* proj_w  = (const float*)d_in[13];
    const float* proj_b  = (const float*)d_in[14];
    const float* ffn1_w  = (const float*)d_in[15];
    const float* ffn1_b  = (const float*)d_in[16];
    const float* ffn2_w  = (const float*)d_in[17];
    const float* ffn2_b  = (const float*)d_in[18];
    float* out = (float*)d_out;

    cudaFuncSetAttribute(k_ln_e0pw, cudaFuncAttributeMaxDynamicSharedMemorySize, S_END);
    cudaFuncSetAttribute(k_proj,    cudaFuncAttributeMaxDynamicSharedMemorySize, S_END);
    cudaFuncSetAttribute(k_ffn1,    cudaFuncAttributeMaxDynamicSharedMemorySize, S_END);
    cudaFuncSetAttribute(k_ffn2,    cudaFuncAttributeMaxDynamicSharedMemorySize, S_END);

    dim3 gg(HW / 64, B_);

    k_ln_e0pw<<<gg, 256, S_END>>>(x, ln_w, ln_b, e0_pw_w, e0_pw_b);

    dim3 gdw(16, C_, B_);
    k_dw<<<gdw, 512>>>(sweights, prompt,
                       e0_dw_w, e0_dw_b, e1_dw_w, e1_dw_b, e2_dw_w, e2_dw_b);

    k_proj<<<gg, 256, S_END>>>(x, proj_w, proj_b);

    k_ffn1<<<gg, 256, S_END>>>(ffn1_w, ffn1_b);

    k_ffn2<<<gg, 256, S_END>>>(ffn2_w, ffn2_b, out);
}